// round 1
// baseline (speedup 1.0000x reference)
#include <cuda_runtime.h>

#define N_NODES 50000
#define N_EDGES 800000
#define NODE_DIM 64
#define HIDDEN 128
#define OUT_DIM 256
#define N_LAYERS 3

// Scratch (static device globals; no allocation at runtime)
__device__ float d_h[(size_t)N_NODES * HIDDEN];    // 25.6 MB
__device__ float d_msg[(size_t)N_NODES * HIDDEN];  // 25.6 MB
__device__ float d_deg[N_NODES];                   // holds deg, then 1/deg
__device__ float d_gsum[HIDDEN];

// ---------------------------------------------------------------------------
__global__ void init_kernel() {
    int i = blockIdx.x * blockDim.x + threadIdx.x;
    if (i < N_NODES) d_deg[i] = 0.0f;
    if (i < HIDDEN) d_gsum[i] = 0.0f;
}

__global__ void deg_kernel(const int* __restrict__ dst) {
    int e = blockIdx.x * blockDim.x + threadIdx.x;
    if (e < N_EDGES) atomicAdd(&d_deg[dst[e]], 1.0f);
}

__global__ void invdeg_kernel() {
    int i = blockIdx.x * blockDim.x + threadIdx.x;
    if (i < N_NODES) {
        float d = d_deg[i];
        d_deg[i] = (d > 0.0f) ? (1.0f / d) : 0.0f;
    }
}

__global__ void zmsg_kernel() {
    int i = blockIdx.x * blockDim.x + threadIdx.x;
    int total = N_NODES * HIDDEN / 4;
    if (i < total) {
        float4 z = make_float4(0.f, 0.f, 0.f, 0.f);
        ((float4*)d_msg)[i] = z;
    }
}

// ---------------------------------------------------------------------------
// h = x @ Wp + bp     (x: [N,64], Wp: [64,128])
// Block: 128 threads, 32 nodes. Thread (nt=t/32, ct=t%32) owns
// nodes nt*8..nt*8+7 and cols ct*4..ct*4+3.
__global__ void proj_kernel(const float* __restrict__ x,
                            const float* __restrict__ Wp,
                            const float* __restrict__ bp) {
    __shared__ float xs[32][NODE_DIM];
    int t = threadIdx.x;
    int node0 = blockIdx.x * 32;

    // Load x tile (32 x 64) via float4; 512 float4s, 128 threads.
    for (int i = t; i < 32 * (NODE_DIM / 4); i += 128) {
        int r = i >> 4;        // /16
        int c4 = i & 15;
        int node = node0 + r;
        float4 v = make_float4(0.f, 0.f, 0.f, 0.f);
        if (node < N_NODES)
            v = ((const float4*)(x + (size_t)node * NODE_DIM))[c4];
        *(float4*)&xs[r][c4 * 4] = v;
    }
    __syncthreads();

    int ct = t & 31;
    int nt = t >> 5;
    int colb = ct * 4;

    float acc[8][4];
#pragma unroll
    for (int i = 0; i < 8; i++)
#pragma unroll
        for (int j = 0; j < 4; j++) acc[i][j] = 0.0f;

    const float4* W4 = (const float4*)Wp;  // Wp[k][c] -> row k = 32 float4
#pragma unroll 8
    for (int k = 0; k < NODE_DIM; k++) {
        float4 w = W4[k * 32 + ct];
#pragma unroll
        for (int i = 0; i < 8; i++) {
            float m = xs[nt * 8 + i][k];
            acc[i][0] += m * w.x;
            acc[i][1] += m * w.y;
            acc[i][2] += m * w.z;
            acc[i][3] += m * w.w;
        }
    }

    float4 bv = ((const float4*)bp)[ct];
#pragma unroll
    for (int i = 0; i < 8; i++) {
        int node = node0 + nt * 8 + i;
        if (node < N_NODES) {
            float4 r;
            r.x = acc[i][0] + bv.x;
            r.y = acc[i][1] + bv.y;
            r.z = acc[i][2] + bv.z;
            r.w = acc[i][3] + bv.w;
            *(float4*)(d_h + (size_t)node * HIDDEN + colb) = r;
        }
    }
}

// ---------------------------------------------------------------------------
// Edge scatter: one warp per edge, lane handles one float4 (32 lanes * 4 = 128).
// Vectorized L2 reduction keeps LTS atomic op count 4x lower than scalar.
__global__ void scatter_kernel(const int* __restrict__ src,
                               const int* __restrict__ dst) {
    int gt = blockIdx.x * blockDim.x + threadIdx.x;
    int e = gt >> 5;
    int lane = gt & 31;
    if (e >= N_EDGES) return;
    int s = src[e];
    int d = dst[e];
    float4 v = ((const float4*)(d_h + (size_t)s * HIDDEN))[lane];
    float* p = d_msg + (size_t)d * HIDDEN + lane * 4;
    asm volatile("red.global.add.v4.f32 [%0], {%1, %2, %3, %4};"
                 :: "l"(p), "f"(v.x), "f"(v.y), "f"(v.z), "f"(v.w)
                 : "memory");
}

// ---------------------------------------------------------------------------
// h = relu(h + (msg * invdeg) @ Wg + bg)    (Wg: [128,128])
// Same register tiling as proj; Wg served from L1 (64 KB resident).
__global__ void gemm_relu_kernel(const float* __restrict__ Wg,
                                 const float* __restrict__ bg) {
    __shared__ float ms[32][HIDDEN];
    int t = threadIdx.x;
    int node0 = blockIdx.x * 32;

    // Load msg tile scaled by invdeg (32 x 128) via float4.
    for (int i = t; i < 32 * (HIDDEN / 4); i += 128) {
        int r = i >> 5;       // /32
        int c4 = i & 31;
        int node = node0 + r;
        float4 v = make_float4(0.f, 0.f, 0.f, 0.f);
        if (node < N_NODES) {
            v = ((const float4*)(d_msg + (size_t)node * HIDDEN))[c4];
            float inv = d_deg[node];
            v.x *= inv; v.y *= inv; v.z *= inv; v.w *= inv;
        }
        *(float4*)&ms[r][c4 * 4] = v;
    }
    __syncthreads();

    int ct = t & 31;
    int nt = t >> 5;
    int colb = ct * 4;

    float acc[8][4];
#pragma unroll
    for (int i = 0; i < 8; i++)
#pragma unroll
        for (int j = 0; j < 4; j++) acc[i][j] = 0.0f;

    const float4* W4 = (const float4*)Wg;
#pragma unroll 8
    for (int k = 0; k < HIDDEN; k++) {
        float4 w = W4[k * 32 + ct];
#pragma unroll
        for (int i = 0; i < 8; i++) {
            float m = ms[nt * 8 + i][k];
            acc[i][0] += m * w.x;
            acc[i][1] += m * w.y;
            acc[i][2] += m * w.z;
            acc[i][3] += m * w.w;
        }
    }

    float4 bv = ((const float4*)bg)[ct];
#pragma unroll
    for (int i = 0; i < 8; i++) {
        int node = node0 + nt * 8 + i;
        if (node < N_NODES) {
            float* hp = d_h + (size_t)node * HIDDEN + colb;
            float4 hv = *(float4*)hp;
            float4 r;
            r.x = fmaxf(hv.x + acc[i][0] + bv.x, 0.0f);
            r.y = fmaxf(hv.y + acc[i][1] + bv.y, 0.0f);
            r.z = fmaxf(hv.z + acc[i][2] + bv.z, 0.0f);
            r.w = fmaxf(hv.w + acc[i][3] + bv.w, 0.0f);
            *(float4*)hp = r;
        }
    }
}

// ---------------------------------------------------------------------------
// Column sums of h into d_gsum (mean applied in MLP kernel).
__global__ void reduce_kernel() {
    int t = threadIdx.x;             // 256 threads
    int col = t & 127;
    int rh = t >> 7;                 // 0 or 1
    float acc = 0.0f;
    for (int node = blockIdx.x * 2 + rh; node < N_NODES; node += gridDim.x * 2)
        acc += d_h[(size_t)node * HIDDEN + col];
    atomicAdd(&d_gsum[col], acc);
}

__global__ void mlp_kernel(const float* __restrict__ W1,
                           const float* __restrict__ b1,
                           const float* __restrict__ W2,
                           const float* __restrict__ b2,
                           float* __restrict__ out) {
    __shared__ float gs[HIDDEN];
    __shared__ float ts[HIDDEN];
    int t = threadIdx.x;  // 256
    if (t < HIDDEN) gs[t] = d_gsum[t] * (1.0f / (float)N_NODES);
    __syncthreads();
    if (t < HIDDEN) {
        float a = b1[t];
#pragma unroll 8
        for (int k = 0; k < HIDDEN; k++) a += gs[k] * W1[k * HIDDEN + t];
        ts[t] = fmaxf(a, 0.0f);
    }
    __syncthreads();
    {
        float a = b2[t];
#pragma unroll 8
        for (int k = 0; k < HIDDEN; k++) a += ts[k] * W2[k * OUT_DIM + t];
        out[t] = a;
    }
}

// ---------------------------------------------------------------------------
extern "C" void kernel_launch(void* const* d_in, const int* in_sizes, int n_in,
                              void* d_out, int out_size) {
    const float* x  = (const float*)d_in[0];
    const int*   src = (const int*)d_in[1];
    const int*   dst = (const int*)d_in[2];
    const float* Wp = (const float*)d_in[3];
    const float* bp = (const float*)d_in[4];
    const float* Wg = (const float*)d_in[5];
    const float* bg = (const float*)d_in[6];
    const float* W1 = (const float*)d_in[7];
    const float* b1 = (const float*)d_in[8];
    const float* W2 = (const float*)d_in[9];
    const float* b2 = (const float*)d_in[10];
    float* out = (float*)d_out;

    init_kernel<<<(N_NODES + 255) / 256, 256>>>();
    proj_kernel<<<(N_NODES + 31) / 32, 128>>>(x, Wp, bp);
    deg_kernel<<<(N_EDGES + 255) / 256, 256>>>(dst);
    invdeg_kernel<<<(N_NODES + 255) / 256, 256>>>();

    for (int l = 0; l < N_LAYERS; l++) {
        zmsg_kernel<<<(N_NODES * HIDDEN / 4 + 255) / 256, 256>>>();
        scatter_kernel<<<(N_EDGES * 32 + 255) / 256, 256>>>(src, dst);
        gemm_relu_kernel<<<(N_NODES + 31) / 32, 128>>>(
            Wg + (size_t)l * HIDDEN * HIDDEN, bg + (size_t)l * HIDDEN);
    }

    reduce_kernel<<<256, 256>>>();
    mlp_kernel<<<1, 256>>>(W1, b1, W2, b2, out);
}

// round 2
// speedup vs baseline: 1.1972x; 1.1972x over previous
#include <cuda_runtime.h>

#define N_NODES 50000
#define N_EDGES 800000
#define NODE_DIM 64
#define HIDDEN 128
#define OUT_DIM 256
#define N_LAYERS 3
#define SCAN_BLOCKS ((N_NODES + 255) / 256)   // 196

// Scratch (static device globals; no runtime allocation)
__device__ float d_hbuf0[(size_t)N_NODES * HIDDEN];
__device__ float d_hbuf1[(size_t)N_NODES * HIDDEN];
__device__ float d_deg[N_NODES];      // 1/deg (0 for isolated nodes)
__device__ float d_gsum[HIDDEN];
__device__ int   d_cnt[N_NODES];      // histogram
__device__ int   d_row[N_NODES + 1];  // CSR row offsets
__device__ int   d_cur[N_NODES];      // fill cursors
__device__ int   d_colA[N_EDGES];     // CSR column (src node per edge slot)
__device__ int   d_bsum[SCAN_BLOCKS];

// ---- packed f32x2 helpers (Blackwell dual-FMA) -----------------------------
__device__ __forceinline__ unsigned long long pack2(float lo, float hi) {
    unsigned long long r;
    asm("mov.b64 %0, {%1, %2};" : "=l"(r)
        : "r"(__float_as_uint(lo)), "r"(__float_as_uint(hi)));
    return r;
}
__device__ __forceinline__ void unpack2(unsigned long long v, float& lo, float& hi) {
    unsigned int a, b;
    asm("mov.b64 {%0, %1}, %2;" : "=r"(a), "=r"(b) : "l"(v));
    lo = __uint_as_float(a);
    hi = __uint_as_float(b);
}
__device__ __forceinline__ void fma2(unsigned long long& acc,
                                     unsigned long long a, unsigned long long b) {
    asm("fma.rn.f32x2 %0, %1, %2, %0;" : "+l"(acc) : "l"(a), "l"(b));
}

// ---------------------------------------------------------------------------
__global__ void init_kernel() {
    int i = blockIdx.x * blockDim.x + threadIdx.x;
    if (i < N_NODES) d_cnt[i] = 0;
    if (i < HIDDEN) d_gsum[i] = 0.0f;
}

__global__ void hist_kernel(const int* __restrict__ dst) {
    int e = blockIdx.x * blockDim.x + threadIdx.x;
    if (e < N_EDGES) atomicAdd(&d_cnt[dst[e]], 1);
}

// Block-level exclusive scan of d_cnt -> d_row (partial), block totals -> d_bsum
__global__ void scan1_kernel() {
    __shared__ int sd[256];
    int t = threadIdx.x;
    int i = blockIdx.x * 256 + t;
    int v = (i < N_NODES) ? d_cnt[i] : 0;
    sd[t] = v;
    __syncthreads();
#pragma unroll
    for (int off = 1; off < 256; off <<= 1) {
        int a = (t >= off) ? sd[t - off] : 0;
        __syncthreads();
        sd[t] += a;
        __syncthreads();
    }
    if (i < N_NODES) d_row[i] = sd[t] - v;   // exclusive
    if (t == 255) d_bsum[blockIdx.x] = sd[t];
}

__global__ void scan2_kernel() {
    __shared__ int sd[256];
    int t = threadIdx.x;
    int v = (t < SCAN_BLOCKS) ? d_bsum[t] : 0;
    sd[t] = v;
    __syncthreads();
#pragma unroll
    for (int off = 1; off < 256; off <<= 1) {
        int a = (t >= off) ? sd[t - off] : 0;
        __syncthreads();
        sd[t] += a;
        __syncthreads();
    }
    if (t < SCAN_BLOCKS) d_bsum[t] = sd[t] - v;  // exclusive
}

// Finish row offsets, init cursors, compute 1/deg.
__global__ void scan3_kernel() {
    int i = blockIdx.x * blockDim.x + threadIdx.x;
    if (i < N_NODES) {
        int r = d_row[i] + d_bsum[blockIdx.x * 256 / 256 == 0 ? blockIdx.x : blockIdx.x];
        r = d_row[i] + d_bsum[blockIdx.x];
        d_row[i] = r;
        d_cur[i] = r;
        int c = d_cnt[i];
        d_deg[i] = (c > 0) ? (1.0f / (float)c) : 0.0f;
    }
    if (i == 0) d_row[N_NODES] = N_EDGES;
}

__global__ void fill_kernel(const int* __restrict__ src, const int* __restrict__ dst) {
    int e = blockIdx.x * blockDim.x + threadIdx.x;
    if (e < N_EDGES) {
        int d = dst[e];
        int pos = atomicAdd(&d_cur[d], 1);
        d_colA[pos] = src[e];
    }
}

// ---------------------------------------------------------------------------
// h0 = x @ Wp + bp     (x: [N,64], Wp: [64,128]) -> d_hbuf0
// 128 threads / 32 nodes; thread (nt,ct) owns 8 nodes x 4 cols; packed fma2.
__global__ void proj_kernel(const float* __restrict__ x,
                            const float* __restrict__ Wp,
                            const float* __restrict__ bp) {
    __shared__ float xs[32][NODE_DIM];
    int t = threadIdx.x;
    int node0 = blockIdx.x * 32;

    for (int i = t; i < 32 * (NODE_DIM / 4); i += 128) {
        int r = i >> 4;
        int c4 = i & 15;
        int node = node0 + r;
        float4 v = make_float4(0.f, 0.f, 0.f, 0.f);
        if (node < N_NODES)
            v = ((const float4*)(x + (size_t)node * NODE_DIM))[c4];
        *(float4*)&xs[r][c4 * 4] = v;
    }
    __syncthreads();

    int ct = t & 31;
    int nt = t >> 5;
    int colb = ct * 4;

    unsigned long long acc2[8][2];
#pragma unroll
    for (int i = 0; i < 8; i++) { acc2[i][0] = 0ull; acc2[i][1] = 0ull; }

    const float4* W4 = (const float4*)Wp;
#pragma unroll 4
    for (int k = 0; k < NODE_DIM; k++) {
        float4 w = W4[k * 32 + ct];
        unsigned long long wp0 = pack2(w.x, w.y);
        unsigned long long wp1 = pack2(w.z, w.w);
#pragma unroll
        for (int i = 0; i < 8; i++) {
            float m = xs[nt * 8 + i][k];
            unsigned long long mp = pack2(m, m);
            fma2(acc2[i][0], mp, wp0);
            fma2(acc2[i][1], mp, wp1);
        }
    }

    float4 bv = ((const float4*)bp)[ct];
#pragma unroll
    for (int i = 0; i < 8; i++) {
        int node = node0 + nt * 8 + i;
        if (node < N_NODES) {
            float4 r;
            unpack2(acc2[i][0], r.x, r.y);
            unpack2(acc2[i][1], r.z, r.w);
            r.x += bv.x; r.y += bv.y; r.z += bv.z; r.w += bv.w;
            *(float4*)(d_hbuf0 + (size_t)node * HIDDEN + colb) = r;
        }
    }
}

// ---------------------------------------------------------------------------
// Fused GNN layer: hout = relu(hin + (gather_mean(hin) @ Wg) + bg)
// Phase 1: CSR gather of neighbor rows into smem (scaled by 1/deg).
// Phase 2: register-tiled GEMM + residual + relu.
// Safe because hin/hout ping-pong (no in-place update).
__global__ void layer_kernel(const float* __restrict__ hin,
                             float* __restrict__ hout,
                             const float* __restrict__ Wg,
                             const float* __restrict__ bg) {
    __shared__ float ms[32][HIDDEN];
    int t = threadIdx.x;
    int node0 = blockIdx.x * 32;
    int lane = t & 31;
    int w = t >> 5;   // warp 0..3

    // Phase 1: warp w gathers nodes node0+w*8 .. +7; lane covers cols lane*4..+3
#pragma unroll 1
    for (int i = 0; i < 8; i++) {
        int nl = w * 8 + i;
        int node = node0 + nl;
        float4 a0 = make_float4(0.f, 0.f, 0.f, 0.f);
        float4 a1 = a0, a2 = a0, a3 = a0;
        if (node < N_NODES) {
            int beg = d_row[node];
            int end = d_row[node + 1];
            int j = beg;
            for (; j + 4 <= end; j += 4) {
                int s0 = d_colA[j], s1 = d_colA[j + 1];
                int s2 = d_colA[j + 2], s3 = d_colA[j + 3];
                float4 v0 = ((const float4*)(hin + (size_t)s0 * HIDDEN))[lane];
                float4 v1 = ((const float4*)(hin + (size_t)s1 * HIDDEN))[lane];
                float4 v2 = ((const float4*)(hin + (size_t)s2 * HIDDEN))[lane];
                float4 v3 = ((const float4*)(hin + (size_t)s3 * HIDDEN))[lane];
                a0.x += v0.x; a0.y += v0.y; a0.z += v0.z; a0.w += v0.w;
                a1.x += v1.x; a1.y += v1.y; a1.z += v1.z; a1.w += v1.w;
                a2.x += v2.x; a2.y += v2.y; a2.z += v2.z; a2.w += v2.w;
                a3.x += v3.x; a3.y += v3.y; a3.z += v3.z; a3.w += v3.w;
            }
            for (; j < end; j++) {
                int s = d_colA[j];
                float4 v = ((const float4*)(hin + (size_t)s * HIDDEN))[lane];
                a0.x += v.x; a0.y += v.y; a0.z += v.z; a0.w += v.w;
            }
            float inv = d_deg[node];
            a0.x = (a0.x + a1.x + a2.x + a3.x) * inv;
            a0.y = (a0.y + a1.y + a2.y + a3.y) * inv;
            a0.z = (a0.z + a1.z + a2.z + a3.z) * inv;
            a0.w = (a0.w + a1.w + a2.w + a3.w) * inv;
        }
        *(float4*)&ms[nl][lane * 4] = a0;
    }
    __syncthreads();

    // Phase 2: (ms @ Wg), thread (nt,ct) owns 8 nodes x 4 cols
    int ct = lane;
    int nt = w;
    int colb = ct * 4;

    unsigned long long acc2[8][2];
#pragma unroll
    for (int i = 0; i < 8; i++) { acc2[i][0] = 0ull; acc2[i][1] = 0ull; }

    const float4* W4 = (const float4*)Wg;
#pragma unroll 4
    for (int k = 0; k < HIDDEN; k++) {
        float4 wv = W4[k * 32 + ct];
        unsigned long long wp0 = pack2(wv.x, wv.y);
        unsigned long long wp1 = pack2(wv.z, wv.w);
#pragma unroll
        for (int i = 0; i < 8; i++) {
            float m = ms[nt * 8 + i][k];
            unsigned long long mp = pack2(m, m);
            fma2(acc2[i][0], mp, wp0);
            fma2(acc2[i][1], mp, wp1);
        }
    }

    float4 bv = ((const float4*)bg)[ct];
#pragma unroll
    for (int i = 0; i < 8; i++) {
        int node = node0 + nt * 8 + i;
        if (node < N_NODES) {
            float4 hv = *(const float4*)(hin + (size_t)node * HIDDEN + colb);
            float4 r;
            unpack2(acc2[i][0], r.x, r.y);
            unpack2(acc2[i][1], r.z, r.w);
            r.x = fmaxf(hv.x + r.x + bv.x, 0.0f);
            r.y = fmaxf(hv.y + r.y + bv.y, 0.0f);
            r.z = fmaxf(hv.z + r.z + bv.z, 0.0f);
            r.w = fmaxf(hv.w + r.w + bv.w, 0.0f);
            *(float4*)(hout + (size_t)node * HIDDEN + colb) = r;
        }
    }
}

// ---------------------------------------------------------------------------
__global__ void reduce_kernel(const float* __restrict__ h) {
    int t = threadIdx.x;   // 256
    int col = t & 127;
    int rh = t >> 7;
    float acc = 0.0f;
    for (int node = blockIdx.x * 2 + rh; node < N_NODES; node += gridDim.x * 2)
        acc += h[(size_t)node * HIDDEN + col];
    atomicAdd(&d_gsum[col], acc);
}

__global__ void mlp_kernel(const float* __restrict__ W1,
                           const float* __restrict__ b1,
                           const float* __restrict__ W2,
                           const float* __restrict__ b2,
                           float* __restrict__ out) {
    __shared__ float gs[HIDDEN];
    __shared__ float ts[HIDDEN];
    int t = threadIdx.x;  // 256
    if (t < HIDDEN) gs[t] = d_gsum[t] * (1.0f / (float)N_NODES);
    __syncthreads();
    if (t < HIDDEN) {
        float a = b1[t];
#pragma unroll 8
        for (int k = 0; k < HIDDEN; k++) a += gs[k] * W1[k * HIDDEN + t];
        ts[t] = fmaxf(a, 0.0f);
    }
    __syncthreads();
    {
        float a = b2[t];
#pragma unroll 8
        for (int k = 0; k < HIDDEN; k++) a += ts[k] * W2[k * OUT_DIM + t];
        out[t] = a;
    }
}

// ---------------------------------------------------------------------------
extern "C" void kernel_launch(void* const* d_in, const int* in_sizes, int n_in,
                              void* d_out, int out_size) {
    const float* x   = (const float*)d_in[0];
    const int*   src = (const int*)d_in[1];
    const int*   dst = (const int*)d_in[2];
    const float* Wp  = (const float*)d_in[3];
    const float* bp  = (const float*)d_in[4];
    const float* Wg  = (const float*)d_in[5];
    const float* bg  = (const float*)d_in[6];
    const float* W1  = (const float*)d_in[7];
    const float* b1  = (const float*)d_in[8];
    const float* W2  = (const float*)d_in[9];
    const float* b2  = (const float*)d_in[10];
    float* out = (float*)d_out;

    float *h0, *h1;
    cudaGetSymbolAddress((void**)&h0, d_hbuf0);
    cudaGetSymbolAddress((void**)&h1, d_hbuf1);

    // CSR build
    init_kernel<<<(N_NODES + 255) / 256, 256>>>();
    hist_kernel<<<(N_EDGES + 255) / 256, 256>>>(dst);
    scan1_kernel<<<SCAN_BLOCKS, 256>>>();
    scan2_kernel<<<1, 256>>>();
    scan3_kernel<<<SCAN_BLOCKS, 256>>>();
    fill_kernel<<<(N_EDGES + 255) / 256, 256>>>(src, dst);

    // node projection
    proj_kernel<<<(N_NODES + 31) / 32, 128>>>(x, Wp, bp);

    // GNN layers with ping-pong buffers: 0->1, 1->0, 0->1
    const int nblocks = (N_NODES + 31) / 32;
    float* bufs[2] = {h0, h1};
    for (int l = 0; l < N_LAYERS; l++) {
        float* hin  = bufs[l & 1];
        float* hout = bufs[(l + 1) & 1];
        layer_kernel<<<nblocks, 128>>>(hin, hout,
                                       Wg + (size_t)l * HIDDEN * HIDDEN,
                                       bg + (size_t)l * HIDDEN);
    }

    // mean over nodes + MLP head (final h is in buf (N_LAYERS & 1) = 1)
    reduce_kernel<<<256, 256>>>(bufs[N_LAYERS & 1]);
    mlp_kernel<<<1, 256>>>(W1, b1, W2, b2, out);
}